// round 12
// baseline (speedup 1.0000x reference)
#include <cuda_runtime.h>
#include <cuda_fp16.h>
#include <cstdint>

// ============================================================================
// PiLinear: out = qz(qz(x) @ qz(W)^T + b), qz(v) = round(v/u)*u, u = (pi/2)/256
//
// Exact-integer path: i = round(x/u), j = round(w/u) exact in f16; f16 MMA
// with f32 accumulation computes S = sum(i*j) exactly. Epilogue reconstructs
// round(S*u)*u (+bias, requantize).
//
// R12: warp-specialized async pipeline. Warp 8 is a dedicated producer
// issuing all cp.async; stage-ready via cp.async.mbarrier.arrive.noinc,
// stage-free via per-consumer-warp mbarrier.arrive. Consumers never
// __syncthreads in the mainloop -- removes the per-k-tile all-warp
// rendezvous (pipe drain + simultaneous LDSM ramp) behind the 18% tensor
// idle measured in R10/R11.
// ============================================================================

#define U_F   0.006135923151542565f   // (pi/2)/256
#define INVU_F 162.97466172610083f    // 512/pi

static constexpr int M_DIM = 8192;
static constexpr int N_DIM = 4096;
static constexpr int K_DIM = 4096;

static constexpr int BM = 128, BN = 256, BK = 128;
static constexpr int KT = K_DIM / BK;                         // 32 k-tiles
static constexpr int A_STAGE_BYTES = BM * BK * 2;             // 32768
static constexpr int B_STAGE_BYTES = BN * BK * 2;             // 65536
static constexpr int STAGE_BYTES = A_STAGE_BYTES + B_STAGE_BYTES;  // 98304
static constexpr uint32_t MBAR_OFF = 2 * STAGE_BYTES;         // 196608
static constexpr int SMEM_SIZE = 2 * STAGE_BYTES + 64;        // 196672

static constexpr int MTILES = M_DIM / BM;   // 64
static constexpr int NTILES = N_DIM / BN;   // 16
static constexpr int TOTAL_TILES = MTILES * NTILES;  // 1024

static constexpr int NTHREADS = 288;        // 8 consumer warps + 1 producer

// Quantized f16-integer operand copies (scratch; no allocation allowed).
static __device__ __align__(128) __half g_A16[(size_t)M_DIM * K_DIM];
static __device__ __align__(128) __half g_B16[(size_t)N_DIM * K_DIM];

// ----------------------------------------------------------------------------
// PTX helpers
// ----------------------------------------------------------------------------
__device__ __forceinline__ uint32_t smem_u32(const void* p) {
    uint32_t a;
    asm("{ .reg .u64 t; cvta.to.shared.u64 t, %1; cvt.u32.u64 %0, t; }"
        : "=r"(a) : "l"(p));
    return a;
}

#define CP_ASYNC16(dst, src) \
    asm volatile("cp.async.cg.shared.global [%0], [%1], 16;" \
                 :: "r"(dst), "l"(src) : "memory")

#define MBAR_INIT(addr, cnt) \
    asm volatile("mbarrier.init.shared.b64 [%0], %1;" :: "r"(addr), "r"(cnt) : "memory")

#define MBAR_ARRIVE(addr) \
    asm volatile("mbarrier.arrive.shared.b64 _, [%0];" :: "r"(addr) : "memory")

// arrive on mbarrier when ALL prior cp.async of this thread complete;
// .noinc consumes one of the pre-initialized expected arrivals.
#define CPASYNC_MBAR_NOINC(addr) \
    asm volatile("cp.async.mbarrier.arrive.noinc.shared.b64 [%0];" \
                 :: "r"(addr) : "memory")

#define MBAR_WAIT(addr, parity) do {                                          \
    uint32_t _m = (addr); uint32_t _p = (parity); uint32_t _d;                \
    asm volatile("{ .reg .pred p;"                                           \
        " mbarrier.try_wait.parity.acquire.cta.shared::cta.b64 p, [%1], %2;" \
        " selp.b32 %0, 1, 0, p; }" : "=r"(_d) : "r"(_m), "r"(_p) : "memory");\
    if (!_d) {                                                                \
        asm volatile("{ .reg .pred P1;"                                      \
        " W%=: mbarrier.try_wait.parity.acquire.cta.shared::cta.b64 P1, [%0], %1, 0x989680;" \
        " @P1 bra.uni D%=; bra.uni W%=; D%=: }" :: "r"(_m), "r"(_p) : "memory"); \
    } } while (0)

#define LDSM4(r, addr) \
    asm volatile("ldmatrix.sync.aligned.m8n8.x4.shared.b16 {%0,%1,%2,%3}, [%4];" \
                 : "=r"((r)[0]), "=r"((r)[1]), "=r"((r)[2]), "=r"((r)[3]) \
                 : "r"(addr))

#define MMA16816(d, a, b0, b1) \
    asm volatile("mma.sync.aligned.m16n8k16.row.col.f32.f16.f16.f32 " \
                 "{%0,%1,%2,%3}, {%4,%5,%6,%7}, {%8,%9}, {%0,%1,%2,%3};" \
                 : "+f"((d)[0]), "+f"((d)[1]), "+f"((d)[2]), "+f"((d)[3]) \
                 : "r"((a)[0]), "r"((a)[1]), "r"((a)[2]), "r"((a)[3]), \
                   "r"(b0), "r"(b1))

// ----------------------------------------------------------------------------
// Merged quantize-to-f16 kernel (74% DRAM roofline; unchanged).
// ----------------------------------------------------------------------------
static constexpr int XBLKS = (int)(((size_t)M_DIM * K_DIM / 8) / 256);  // 16384
static constexpr int WBLKS = (int)(((size_t)N_DIM * K_DIM / 8) / 256);  // 8192

__global__ void __launch_bounds__(256) quant2_kernel(
    const float* __restrict__ x, __half* __restrict__ a,
    const float* __restrict__ wgt, __half* __restrict__ b) {
    const int bid = blockIdx.x;
    const float* s;
    __half* d;
    size_t base;
    if (bid < XBLKS) { s = x;   d = a; base = (size_t)bid * 2048; }
    else             { s = wgt; d = b; base = (size_t)(bid - XBLKS) * 2048; }
    const size_t i = base + (size_t)threadIdx.x * 8;
    const float4 v0 = *reinterpret_cast<const float4*>(s + i);
    const float4 v1 = *reinterpret_cast<const float4*>(s + i + 4);
    unsigned short h[8];
    h[0] = __half_as_ushort(__float2half_rn(rintf(__fdiv_rn(v0.x, U_F))));
    h[1] = __half_as_ushort(__float2half_rn(rintf(__fdiv_rn(v0.y, U_F))));
    h[2] = __half_as_ushort(__float2half_rn(rintf(__fdiv_rn(v0.z, U_F))));
    h[3] = __half_as_ushort(__float2half_rn(rintf(__fdiv_rn(v0.w, U_F))));
    h[4] = __half_as_ushort(__float2half_rn(rintf(__fdiv_rn(v1.x, U_F))));
    h[5] = __half_as_ushort(__float2half_rn(rintf(__fdiv_rn(v1.y, U_F))));
    h[6] = __half_as_ushort(__float2half_rn(rintf(__fdiv_rn(v1.z, U_F))));
    h[7] = __half_as_ushort(__float2half_rn(rintf(__fdiv_rn(v1.w, U_F))));
    uint4 p;
    p.x = (uint32_t)h[0] | ((uint32_t)h[1] << 16);
    p.y = (uint32_t)h[2] | ((uint32_t)h[3] << 16);
    p.z = (uint32_t)h[4] | ((uint32_t)h[5] << 16);
    p.w = (uint32_t)h[6] | ((uint32_t)h[7] << 16);
    *reinterpret_cast<uint4*>(d + i) = p;
}

// Per-thread chunk strides (256B smem rows, 16 rows per chunk step).
static constexpr size_t SRC_STEP = (size_t)16 * K_DIM;   // halves
static constexpr uint32_t DST_STEP = 16 * 256;           // bytes

// banded rasterization: 8 m-tiles x 16 n-tiles per band (128 tiles/band)
__device__ __forceinline__ void tile_mn(int t, int& mb, int& nb) {
    const int band = t >> 7;
    const int rem = t & 127;
    mb = (band * 8 + (rem & 7)) * BM;
    nb = (rem >> 3) * BN;
}

// ----------------------------------------------------------------------------
// Warp-specialized persistent GEMM. Warps 0-7: consumers (64x64 mma tiles).
// Warp 8: producer (all cp.async). 2-stage ring; full[s] flips via
// cp.async.mbarrier.arrive.noinc (32 producer threads), empty[s] via one
// arrive per consumer warp (8). Consumers have NO __syncthreads in the loop.
// ----------------------------------------------------------------------------
__global__ void __launch_bounds__(NTHREADS, 1)
gemm_kernel(const float* __restrict__ bias, float* __restrict__ out) {
    extern __shared__ __align__(1024) char smem[];
    const uint32_t sbase = smem_u32(smem);
    const uint32_t mb0 = sbase + MBAR_OFF;   // full[0],full[1],empty[0],empty[1]
    const int tid = threadIdx.x;
    const int grid = gridDim.x;

    if (tid == 0) {
        MBAR_INIT(mb0 + 0, 32);   // full[0]
        MBAR_INIT(mb0 + 8, 32);   // full[1]
        MBAR_INIT(mb0 + 16, 8);   // empty[0]
        MBAR_INIT(mb0 + 24, 8);   // empty[1]
    }
    __syncthreads();

    if (tid >= 256) {
        // ==================== PRODUCER (warp 8) ====================
        const int pt = tid - 256;               // 0..31
        int gk = 0;
        for (int tile = blockIdx.x; tile < TOTAL_TILES; tile += grid) {
            int mbase, nbase;
            tile_mn(tile, mbase, nbase);
            const __half* baseA = g_A16 + (size_t)mbase * K_DIM;
            const __half* baseB = g_B16 + (size_t)nbase * K_DIM;
            for (int kt = 0; kt < KT; kt++) {
                const int s = gk & 1;
                const uint32_t ph = (uint32_t)(((gk >> 1) & 1) ^ 1);
                MBAR_WAIT(mb0 + 16 + s * 8, ph);           // stage free?
                const uint32_t stA = sbase + s * STAGE_BYTES;
                const int kb = kt * BK;
#pragma unroll
                for (int g = 0; g < 8; g++) {
                    const int ot = pt + 32 * g;            // 0..255
                    const int row0 = ot >> 4;              // 0..15
                    const int c16 = ot & 15;
                    const uint32_t toff = (uint32_t)(row0 * 256 +
                                           ((c16 ^ row0) << 4));
                    const __half* sA = baseA + (size_t)row0 * K_DIM + kb + c16 * 8;
                    const __half* sB = baseB + (size_t)row0 * K_DIM + kb + c16 * 8;
                    const uint32_t dA = stA + toff;
                    const uint32_t dB = dA + A_STAGE_BYTES;
#pragma unroll
                    for (int i = 0; i < 8; i++)
                        CP_ASYNC16(dA + i * DST_STEP, sA + (size_t)i * SRC_STEP);
#pragma unroll
                    for (int i = 0; i < 16; i++)
                        CP_ASYNC16(dB + i * DST_STEP, sB + (size_t)i * SRC_STEP);
                }
                CPASYNC_MBAR_NOINC(mb0 + s * 8);           // signal full when done
                gk++;
            }
        }
        return;
    }

    // ==================== CONSUMERS (warps 0-7) ====================
    const int lane = tid & 31;
    const int w = tid >> 5;
    const int mwarp = w >> 2;        // 0..1 -> 64-row slices
    const int nwarp = w & 3;         // 0..3 -> 64-col slices

    const int x15a = lane & 15;                              // A row mod 16
    const int x15b = (lane & 7) | (((lane >> 4) & 1) << 3);  // B row mod 16
    uint32_t aoff[4], boff[4];
#pragma unroll
    for (int mi = 0; mi < 4; mi++)
        aoff[mi] = (uint32_t)((mwarp * 64 + mi * 16 + x15a) << 8);
#pragma unroll
    for (int nb = 0; nb < 4; nb++)
        boff[nb] = (uint32_t)(A_STAGE_BYTES + ((nwarp * 64 + nb * 16 + x15b) << 8));
    const int acol = lane >> 4;
    const int bcol = (lane >> 3) & 1;
    const int tr = lane >> 2;
    const int tc = (lane & 3) * 2;

    float acc[4][8][4];
#pragma unroll
    for (int mi = 0; mi < 4; mi++)
#pragma unroll
        for (int nj = 0; nj < 8; nj++)
#pragma unroll
            for (int e = 0; e < 4; e++) acc[mi][nj][e] = 0.f;

    int gk = 0;

    for (int tile = blockIdx.x; tile < TOTAL_TILES; tile += grid) {
        int mbase, nbase;
        tile_mn(tile, mbase, nbase);

        for (int kt = 0; kt < KT; kt++) {
            const int s = gk & 1;
            const uint32_t ph = (uint32_t)((gk >> 1) & 1);
            MBAR_WAIT(mb0 + s * 8, ph);                    // stage ready?
            const uint32_t st = sbase + s * STAGE_BYTES;
#pragma unroll
            for (int ks = 0; ks < 8; ks++) {
                uint32_t a[4][4], b[4][4];
#pragma unroll
                for (int nb = 0; nb < 4; nb++)
                    LDSM4(b[nb], st + boff[nb] +
                          ((uint32_t)((ks * 2 + bcol) ^ x15b) << 4));
#pragma unroll
                for (int mi = 0; mi < 4; mi++)
                    LDSM4(a[mi], st + aoff[mi] +
                          ((uint32_t)((ks * 2 + acol) ^ x15a) << 4));
#pragma unroll
                for (int mi = 0; mi < 4; mi++)
#pragma unroll
                    for (int nj = 0; nj < 8; nj++)
                        MMA16816(acc[mi][nj], a[mi],
                                 b[nj >> 1][(nj & 1) * 2], b[nj >> 1][(nj & 1) * 2 + 1]);
            }
            if (lane == 0) MBAR_ARRIVE(mb0 + 16 + s * 8);  // stage free
            gk++;
        }

        // ---- epilogue (producer keeps loading the next tile meanwhile) ----
        const int row0 = mbase + mwarp * 64;
        const int col0 = nbase + nwarp * 64;
        float bv[16];
#pragma unroll
        for (int nj = 0; nj < 8; nj++) {
            bv[nj * 2]     = __ldg(bias + col0 + nj * 8 + tc);
            bv[nj * 2 + 1] = __ldg(bias + col0 + nj * 8 + tc + 1);
        }
#pragma unroll
        for (int mi = 0; mi < 4; mi++) {
#pragma unroll
            for (int rr = 0; rr < 2; rr++) {
                const int row = row0 + mi * 16 + rr * 8 + tr;
                float* orow = out + (size_t)row * N_DIM + col0;
#pragma unroll
                for (int nj = 0; nj < 8; nj++) {
                    const int c = nj * 8 + tc;
                    float2 o;
#pragma unroll
                    for (int e = 0; e < 2; e++) {
                        const float sv = acc[mi][nj][rr * 2 + e];    // exact int S
                        const float q  = rintf(__fmul_rn(sv, U_F)); // round(S*u)
                        const float cv = __fmul_rn(q, U_F);         // qz(dot)
                        const float tv = cv + bv[nj * 2 + e];       // + bias
                        (&o.x)[e] = __fmul_rn(rintf(__fmul_rn(tv, INVU_F)), U_F);
                    }
                    *reinterpret_cast<float2*>(orow + c) = o;
                }
            }
        }
#pragma unroll
        for (int mi = 0; mi < 4; mi++)
#pragma unroll
            for (int nj = 0; nj < 8; nj++)
#pragma unroll
                for (int e = 0; e < 4; e++) acc[mi][nj][e] = 0.f;
    }
}

// ----------------------------------------------------------------------------
// Host launcher (graph-capturable: kernel launches only)
// ----------------------------------------------------------------------------
extern "C" void kernel_launch(void* const* d_in, const int* in_sizes, int n_in,
                              void* d_out, int out_size) {
    const float* x = (const float*)d_in[0];   // [8192, 4096]
    const float* wgt = (const float*)d_in[1]; // [4096, 4096]
    const float* b = (const float*)d_in[2];   // [4096]
    float* out = (float*)d_out;               // [8192, 4096]

    void* a16 = nullptr; void* b16 = nullptr;
    cudaGetSymbolAddress(&a16, g_A16);
    cudaGetSymbolAddress(&b16, g_B16);

    quant2_kernel<<<XBLKS + WBLKS, 256>>>(x, (__half*)a16, wgt, (__half*)b16);

    static int sm_count = 0;
    if (sm_count == 0) {
        cudaDeviceGetAttribute(&sm_count, cudaDevAttrMultiProcessorCount, 0);
        if (sm_count <= 0) sm_count = 148;
        cudaFuncSetAttribute(gemm_kernel,
                             cudaFuncAttributeMaxDynamicSharedMemorySize, SMEM_SIZE);
    }
    gemm_kernel<<<sm_count, NTHREADS, SMEM_SIZE>>>(b, out);
}

// round 13
// speedup vs baseline: 1.1558x; 1.1558x over previous
#include <cuda_runtime.h>
#include <cuda_fp16.h>
#include <cstdint>

// ============================================================================
// PiLinear: out = qz(qz(x) @ qz(W)^T + b), qz(v) = round(v/u)*u, u = (pi/2)/256
//
// Exact-integer path: i = round(x/u), j = round(w/u) exact in f16; f16 MMA
// with f32 accumulation computes S = sum(i*j) exactly. Epilogue reconstructs
// round(S*u)*u (+bias, requantize).
//
// R13 = R11 (revert of the R12 warp-specialization regression) with the
// next-stage loads compressed to 8 chunks per micro-step, commit at ks=2:
// one extra micro-step (~512cy) of cp.async completion margin before the
// next wait_group 0, targeting the ~750cy/kt late-completion idle.
// ============================================================================

#define U_F   0.006135923151542565f   // (pi/2)/256
#define INVU_F 162.97466172610083f    // 512/pi

static constexpr int M_DIM = 8192;
static constexpr int N_DIM = 4096;
static constexpr int K_DIM = 4096;

static constexpr int BM = 128, BN = 256, BK = 128;
static constexpr int KT = K_DIM / BK;                         // 32 k-tiles
static constexpr int A_STAGE_BYTES = BM * BK * 2;             // 32768
static constexpr int B_STAGE_BYTES = BN * BK * 2;             // 65536
static constexpr int STAGE_BYTES = A_STAGE_BYTES + B_STAGE_BYTES;  // 98304
static constexpr int SMEM_SIZE = 2 * STAGE_BYTES;             // 196608

static constexpr int MTILES = M_DIM / BM;   // 64
static constexpr int NTILES = N_DIM / BN;   // 16
static constexpr int TOTAL_TILES = MTILES * NTILES;  // 1024

// Quantized f16-integer operand copies (scratch; no allocation allowed).
static __device__ __align__(128) __half g_A16[(size_t)M_DIM * K_DIM];
static __device__ __align__(128) __half g_B16[(size_t)N_DIM * K_DIM];

// ----------------------------------------------------------------------------
// PTX helpers
// ----------------------------------------------------------------------------
__device__ __forceinline__ uint32_t smem_u32(const void* p) {
    uint32_t a;
    asm("{ .reg .u64 t; cvta.to.shared.u64 t, %1; cvt.u32.u64 %0, t; }"
        : "=r"(a) : "l"(p));
    return a;
}

#define CP_ASYNC16(dst, src) \
    asm volatile("cp.async.cg.shared.global [%0], [%1], 16;" \
                 :: "r"(dst), "l"(src) : "memory")
#define CP_COMMIT() asm volatile("cp.async.commit_group;" ::: "memory")
#define CP_WAIT0()  asm volatile("cp.async.wait_group 0;"  ::: "memory")

#define LDSM4(r, addr) \
    asm volatile("ldmatrix.sync.aligned.m8n8.x4.shared.b16 {%0,%1,%2,%3}, [%4];" \
                 : "=r"((r)[0]), "=r"((r)[1]), "=r"((r)[2]), "=r"((r)[3]) \
                 : "r"(addr))

#define MMA16816(d, a, b0, b1) \
    asm volatile("mma.sync.aligned.m16n8k16.row.col.f32.f16.f16.f32 " \
                 "{%0,%1,%2,%3}, {%4,%5,%6,%7}, {%8,%9}, {%0,%1,%2,%3};" \
                 : "+f"((d)[0]), "+f"((d)[1]), "+f"((d)[2]), "+f"((d)[3]) \
                 : "r"((a)[0]), "r"((a)[1]), "r"((a)[2]), "r"((a)[3]), \
                   "r"(b0), "r"(b1))

// ----------------------------------------------------------------------------
// Merged quantize-to-f16 kernel (74% DRAM roofline; unchanged).
// ----------------------------------------------------------------------------
static constexpr int XBLKS = (int)(((size_t)M_DIM * K_DIM / 8) / 256);  // 16384
static constexpr int WBLKS = (int)(((size_t)N_DIM * K_DIM / 8) / 256);  // 8192

__global__ void __launch_bounds__(256) quant2_kernel(
    const float* __restrict__ x, __half* __restrict__ a,
    const float* __restrict__ wgt, __half* __restrict__ b) {
    const int bid = blockIdx.x;
    const float* s;
    __half* d;
    size_t base;
    if (bid < XBLKS) { s = x;   d = a; base = (size_t)bid * 2048; }
    else             { s = wgt; d = b; base = (size_t)(bid - XBLKS) * 2048; }
    const size_t i = base + (size_t)threadIdx.x * 8;
    const float4 v0 = *reinterpret_cast<const float4*>(s + i);
    const float4 v1 = *reinterpret_cast<const float4*>(s + i + 4);
    unsigned short h[8];
    h[0] = __half_as_ushort(__float2half_rn(rintf(__fdiv_rn(v0.x, U_F))));
    h[1] = __half_as_ushort(__float2half_rn(rintf(__fdiv_rn(v0.y, U_F))));
    h[2] = __half_as_ushort(__float2half_rn(rintf(__fdiv_rn(v0.z, U_F))));
    h[3] = __half_as_ushort(__float2half_rn(rintf(__fdiv_rn(v0.w, U_F))));
    h[4] = __half_as_ushort(__float2half_rn(rintf(__fdiv_rn(v1.x, U_F))));
    h[5] = __half_as_ushort(__float2half_rn(rintf(__fdiv_rn(v1.y, U_F))));
    h[6] = __half_as_ushort(__float2half_rn(rintf(__fdiv_rn(v1.z, U_F))));
    h[7] = __half_as_ushort(__float2half_rn(rintf(__fdiv_rn(v1.w, U_F))));
    uint4 p;
    p.x = (uint32_t)h[0] | ((uint32_t)h[1] << 16);
    p.y = (uint32_t)h[2] | ((uint32_t)h[3] << 16);
    p.z = (uint32_t)h[4] | ((uint32_t)h[5] << 16);
    p.w = (uint32_t)h[6] | ((uint32_t)h[7] << 16);
    *reinterpret_cast<uint4*>(d + i) = p;
}

// Per-thread chunk strides (256B smem rows, 16 rows per chunk step).
static constexpr size_t SRC_STEP = (size_t)16 * K_DIM;   // halves
static constexpr uint32_t DST_STEP = 16 * 256;           // bytes

#define LOAD_A(i) CP_ASYNC16(dA + (i) * DST_STEP, srcA + (size_t)(i) * SRC_STEP)
#define LOAD_B(i) CP_ASYNC16(dB + (i) * DST_STEP, srcB + (size_t)(i) * SRC_STEP)

// banded rasterization: 8 m-tiles x 16 n-tiles per band (128 tiles/band)
__device__ __forceinline__ void tile_mn(int t, int& mb, int& nb) {
    const int band = t >> 7;
    const int rem = t & 127;
    mb = (band * 8 + (rem & 7)) * BM;
    nb = (rem >> 3) * BN;
}

// ----------------------------------------------------------------------------
// Persistent GEMM: 128x256x128 CTA tile, 2-stage cp.async ring continuous
// across tiles, 8 warps (2M x 4N), warp tile 64x64 mma.sync m16n8k16,
// fused pi-quantize epilogue overlapped with the next tile's loads.
// ----------------------------------------------------------------------------
__global__ void __launch_bounds__(256, 1)
gemm_kernel(const float* __restrict__ bias, float* __restrict__ out) {
    extern __shared__ __align__(1024) char smem[];
    const uint32_t sbase = smem_u32(smem);
    const int tid = threadIdx.x;
    const int lane = tid & 31;
    const int w = tid >> 5;
    const int grid = gridDim.x;

    // per-thread loader constants
    const uint32_t toff = ((uint32_t)(tid >> 4) << 8) +
                          ((uint32_t)((tid & 15) ^ ((tid >> 4) & 15)) << 4);
    const int trow = tid >> 4;
    const int tk8  = (tid & 15) * 8;

    // ---- load cursor: one k-stage ahead, continuous across tiles ----
    int ld_tile = blockIdx.x;
    int ld_k = 0;
    int lmb, lnb;
    tile_mn(ld_tile, lmb, lnb);
    const __half* srcA = g_A16 + (size_t)(lmb + trow) * K_DIM + tk8;
    const __half* srcB = g_B16 + (size_t)(lnb + trow) * K_DIM + tk8;

    // prologue: fill stage 0 with first tile's kt0
    {
        const uint32_t dA = sbase + toff;
        const uint32_t dB = dA + A_STAGE_BYTES;
#pragma unroll
        for (int i = 0; i < 8; i++)  LOAD_A(i);
#pragma unroll
        for (int i = 0; i < 16; i++) LOAD_B(i);
        CP_COMMIT();
    }
    // advance cursor to kt1 of first tile
    ld_k = BK; srcA += BK; srcB += BK;

    const int mwarp = w >> 2;        // 0..1 -> 64-row slices
    const int nwarp = w & 3;         // 0..3 -> 64-col slices

    const int x15a = lane & 15;                              // A row mod 16
    const int x15b = (lane & 7) | (((lane >> 4) & 1) << 3);  // B row mod 16
    uint32_t aoff[4], boff[4];
#pragma unroll
    for (int mi = 0; mi < 4; mi++)
        aoff[mi] = (uint32_t)((mwarp * 64 + mi * 16 + x15a) << 8);
#pragma unroll
    for (int nb = 0; nb < 4; nb++)
        boff[nb] = (uint32_t)(A_STAGE_BYTES + ((nwarp * 64 + nb * 16 + x15b) << 8));
    const int acol = lane >> 4;
    const int bcol = (lane >> 3) & 1;

    const int tr = lane >> 2;
    const int tc = (lane & 3) * 2;

    float acc[4][8][4];
#pragma unroll
    for (int mi = 0; mi < 4; mi++)
#pragma unroll
        for (int nj = 0; nj < 8; nj++)
#pragma unroll
            for (int e = 0; e < 4; e++) acc[mi][nj][e] = 0.f;

    int gk = 0;   // global k counter -> stage parity, continuous across tiles

    for (int tile = blockIdx.x; tile < TOTAL_TILES; tile += grid) {
        int mbase, nbase;
        tile_mn(tile, mbase, nbase);

        for (int kt = 0; kt < KT; kt++) {
            CP_WAIT0();
            __syncthreads();
            const int cur = gk & 1;
            const uint32_t st = sbase + cur * STAGE_BYTES;
            const uint32_t dA = sbase + (cur ^ 1) * STAGE_BYTES + toff;
            const uint32_t dB = dA + A_STAGE_BYTES;
            const bool more = (ld_tile < TOTAL_TILES);
#pragma unroll
            for (int ks = 0; ks < 8; ks++) {
                uint32_t a[4][4], b[4][4];
#pragma unroll
                for (int nb = 0; nb < 4; nb++)
                    LDSM4(b[nb], st + boff[nb] +
                          ((uint32_t)((ks * 2 + bcol) ^ x15b) << 4));
#pragma unroll
                for (int mi = 0; mi < 4; mi++)
                    LDSM4(a[mi], st + aoff[mi] +
                          ((uint32_t)((ks * 2 + acol) ^ x15a) << 4));
#pragma unroll
                for (int mi = 0; mi < 4; mi++)
#pragma unroll
                    for (int nj = 0; nj < 8; nj++)
                        MMA16816(acc[mi][nj], a[mi],
                                 b[nj >> 1][(nj & 1) * 2], b[nj >> 1][(nj & 1) * 2 + 1]);
                // next-stage loads: 8 chunks at ks=0,1,2; commit at ks=2
                if (more) {
                    switch (ks) {
                        case 0:
                            LOAD_A(0); LOAD_A(1); LOAD_A(2); LOAD_A(3);
                            LOAD_A(4); LOAD_A(5); LOAD_A(6); LOAD_A(7);
                            break;
                        case 1:
                            LOAD_B(0); LOAD_B(1); LOAD_B(2); LOAD_B(3);
                            LOAD_B(4); LOAD_B(5); LOAD_B(6); LOAD_B(7);
                            break;
                        case 2:
                            LOAD_B(8);  LOAD_B(9);  LOAD_B(10); LOAD_B(11);
                            LOAD_B(12); LOAD_B(13); LOAD_B(14); LOAD_B(15);
                            CP_COMMIT();
                            break;
                        default: break;
                    }
                }
            }
            gk++;
            // advance load cursor (one k-stage ahead; crosses tile boundary)
            if (more) {
                ld_k += BK;
                if (ld_k == K_DIM) {
                    ld_k = 0;
                    ld_tile += grid;
                    if (ld_tile < TOTAL_TILES) {
                        tile_mn(ld_tile, lmb, lnb);
                        srcA = g_A16 + (size_t)(lmb + trow) * K_DIM + tk8;
                        srcB = g_B16 + (size_t)(lnb + trow) * K_DIM + tk8;
                    }
                } else {
                    srcA += BK;
                    srcB += BK;
                }
            }
        }

        // ---- epilogue (overlaps the next tile's in-flight loads) ----
        const int row0 = mbase + mwarp * 64;
        const int col0 = nbase + nwarp * 64;
        float bv[16];
#pragma unroll
        for (int nj = 0; nj < 8; nj++) {
            bv[nj * 2]     = __ldg(bias + col0 + nj * 8 + tc);
            bv[nj * 2 + 1] = __ldg(bias + col0 + nj * 8 + tc + 1);
        }
#pragma unroll
        for (int mi = 0; mi < 4; mi++) {
#pragma unroll
            for (int rr = 0; rr < 2; rr++) {
                const int row = row0 + mi * 16 + rr * 8 + tr;
                float* orow = out + (size_t)row * N_DIM + col0;
#pragma unroll
                for (int nj = 0; nj < 8; nj++) {
                    const int c = nj * 8 + tc;
                    float2 o;
#pragma unroll
                    for (int e = 0; e < 2; e++) {
                        const float sv = acc[mi][nj][rr * 2 + e];    // exact int S
                        const float q  = rintf(__fmul_rn(sv, U_F)); // round(S*u)
                        const float cv = __fmul_rn(q, U_F);         // qz(dot)
                        const float tv = cv + bv[nj * 2 + e];       // + bias
                        (&o.x)[e] = __fmul_rn(rintf(__fmul_rn(tv, INVU_F)), U_F);
                    }
                    *reinterpret_cast<float2*>(orow + c) = o;
                }
            }
        }
        // reset accumulators for the next tile
#pragma unroll
        for (int mi = 0; mi < 4; mi++)
#pragma unroll
            for (int nj = 0; nj < 8; nj++)
#pragma unroll
                for (int e = 0; e < 4; e++) acc[mi][nj][e] = 0.f;
    }
}

// ----------------------------------------------------------------------------
// Host launcher (graph-capturable: kernel launches only)
// ----------------------------------------------------------------------------
extern "C" void kernel_launch(void* const* d_in, const int* in_sizes, int n_in,
                              void* d_out, int out_size) {
    const float* x = (const float*)d_in[0];   // [8192, 4096]
    const float* wgt = (const float*)d_in[1]; // [4096, 4096]
    const float* b = (const float*)d_in[2];   // [4096]
    float* out = (float*)d_out;               // [8192, 4096]

    void* a16 = nullptr; void* b16 = nullptr;
    cudaGetSymbolAddress(&a16, g_A16);
    cudaGetSymbolAddress(&b16, g_B16);

    quant2_kernel<<<XBLKS + WBLKS, 256>>>(x, (__half*)a16, wgt, (__half*)b16);

    static int sm_count = 0;
    if (sm_count == 0) {
        cudaDeviceGetAttribute(&sm_count, cudaDevAttrMultiProcessorCount, 0);
        if (sm_count <= 0) sm_count = 148;
        cudaFuncSetAttribute(gemm_kernel,
                             cudaFuncAttributeMaxDynamicSharedMemorySize, SMEM_SIZE);
    }
    gemm_kernel<<<sm_count, 256, SMEM_SIZE>>>(b, out);
}

// round 14
// speedup vs baseline: 1.1568x; 1.0008x over previous
#include <cuda_runtime.h>
#include <cuda_fp16.h>
#include <cstdint>

// ============================================================================
// PiLinear: out = qz(qz(x) @ qz(W)^T + b), qz(v) = round(v/u)*u, u = (pi/2)/256
//
// Exact-integer path: i = round(x/u), j = round(w/u) exact in f16; f16 MMA
// with f32 accumulation computes S = sum(i*j) exactly. Epilogue reconstructs
// round(S*u)*u (+bias, requantize).
//
// R14: GEMM mainloop is converged (tensor% invariant at 81.5 across four
// schedule variants -> HMMA-issue floor). GEMM kept bit-identical to the
// 606.8us best. Quant kernel reworked: 16 elems/thread, MLP=4 independent
// __ldcs float4 loads (streaming: inputs never re-read; keeps A16/B16 warm
// in L2 for the GEMM), 512 threads, 6144 blocks.
// ============================================================================

#define U_F   0.006135923151542565f   // (pi/2)/256
#define INVU_F 162.97466172610083f    // 512/pi

static constexpr int M_DIM = 8192;
static constexpr int N_DIM = 4096;
static constexpr int K_DIM = 4096;

static constexpr int BM = 128, BN = 256, BK = 128;
static constexpr int KT = K_DIM / BK;                         // 32 k-tiles
static constexpr int A_STAGE_BYTES = BM * BK * 2;             // 32768
static constexpr int B_STAGE_BYTES = BN * BK * 2;             // 65536
static constexpr int STAGE_BYTES = A_STAGE_BYTES + B_STAGE_BYTES;  // 98304
static constexpr int SMEM_SIZE = 2 * STAGE_BYTES;             // 196608

static constexpr int MTILES = M_DIM / BM;   // 64
static constexpr int NTILES = N_DIM / BN;   // 16
static constexpr int TOTAL_TILES = MTILES * NTILES;  // 1024

// Quantized f16-integer operand copies (scratch; no allocation allowed).
static __device__ __align__(128) __half g_A16[(size_t)M_DIM * K_DIM];
static __device__ __align__(128) __half g_B16[(size_t)N_DIM * K_DIM];

// ----------------------------------------------------------------------------
// PTX helpers
// ----------------------------------------------------------------------------
__device__ __forceinline__ uint32_t smem_u32(const void* p) {
    uint32_t a;
    asm("{ .reg .u64 t; cvta.to.shared.u64 t, %1; cvt.u32.u64 %0, t; }"
        : "=r"(a) : "l"(p));
    return a;
}

#define CP_ASYNC16(dst, src) \
    asm volatile("cp.async.cg.shared.global [%0], [%1], 16;" \
                 :: "r"(dst), "l"(src) : "memory")
#define CP_COMMIT() asm volatile("cp.async.commit_group;" ::: "memory")
#define CP_WAIT0()  asm volatile("cp.async.wait_group 0;"  ::: "memory")

#define LDSM4(r, addr) \
    asm volatile("ldmatrix.sync.aligned.m8n8.x4.shared.b16 {%0,%1,%2,%3}, [%4];" \
                 : "=r"((r)[0]), "=r"((r)[1]), "=r"((r)[2]), "=r"((r)[3]) \
                 : "r"(addr))

#define MMA16816(d, a, b0, b1) \
    asm volatile("mma.sync.aligned.m16n8k16.row.col.f32.f16.f16.f32 " \
                 "{%0,%1,%2,%3}, {%4,%5,%6,%7}, {%8,%9}, {%0,%1,%2,%3};" \
                 : "+f"((d)[0]), "+f"((d)[1]), "+f"((d)[2]), "+f"((d)[3]) \
                 : "r"((a)[0]), "r"((a)[1]), "r"((a)[2]), "r"((a)[3]), \
                   "r"(b0), "r"(b1))

// ----------------------------------------------------------------------------
// Quantize-to-f16 kernel, v2: 512 threads, 16 elems/thread, MLP=4 streaming
// float4 loads. x -> A16 (4096 blocks), w -> B16 (2048 blocks).
// ----------------------------------------------------------------------------
static constexpr int QX_BLKS = (int)(((size_t)M_DIM * K_DIM) / 8192);  // 4096
static constexpr int QW_BLKS = (int)(((size_t)N_DIM * K_DIM) / 8192);  // 2048

__device__ __forceinline__ uint2 quant_pack4(float4 v) {
    unsigned short h0 = __half_as_ushort(__float2half_rn(rintf(__fdiv_rn(v.x, U_F))));
    unsigned short h1 = __half_as_ushort(__float2half_rn(rintf(__fdiv_rn(v.y, U_F))));
    unsigned short h2 = __half_as_ushort(__float2half_rn(rintf(__fdiv_rn(v.z, U_F))));
    unsigned short h3 = __half_as_ushort(__float2half_rn(rintf(__fdiv_rn(v.w, U_F))));
    uint2 p;
    p.x = (uint32_t)h0 | ((uint32_t)h1 << 16);
    p.y = (uint32_t)h2 | ((uint32_t)h3 << 16);
    return p;
}

__global__ void __launch_bounds__(512) quant2_kernel(
    const float* __restrict__ x, __half* __restrict__ a,
    const float* __restrict__ wgt, __half* __restrict__ b) {
    const int bid = blockIdx.x;
    const float* s;
    __half* d;
    size_t base;
    if (bid < QX_BLKS) { s = x;   d = a; base = (size_t)bid * 8192; }
    else               { s = wgt; d = b; base = (size_t)(bid - QX_BLKS) * 8192; }
    const size_t i = base + (size_t)threadIdx.x * 16;

    // 4 independent streaming loads in flight (MLP=4); inputs never re-read.
    const float4* sp = reinterpret_cast<const float4*>(s + i);
    float4 v0 = __ldcs(sp + 0);
    float4 v1 = __ldcs(sp + 1);
    float4 v2 = __ldcs(sp + 2);
    float4 v3 = __ldcs(sp + 3);

    uint2 p0 = quant_pack4(v0);
    uint2 p1 = quant_pack4(v1);
    uint2 p2 = quant_pack4(v2);
    uint2 p3 = quant_pack4(v3);

    uint4* dp = reinterpret_cast<uint4*>(d + i);
    dp[0] = make_uint4(p0.x, p0.y, p1.x, p1.y);
    dp[1] = make_uint4(p2.x, p2.y, p3.x, p3.y);
}

// Per-thread chunk strides (256B smem rows, 16 rows per chunk step).
static constexpr size_t SRC_STEP = (size_t)16 * K_DIM;   // halves
static constexpr uint32_t DST_STEP = 16 * 256;           // bytes

#define LOAD_A(i) CP_ASYNC16(dA + (i) * DST_STEP, srcA + (size_t)(i) * SRC_STEP)
#define LOAD_B(i) CP_ASYNC16(dB + (i) * DST_STEP, srcB + (size_t)(i) * SRC_STEP)

// banded rasterization: 8 m-tiles x 16 n-tiles per band (128 tiles/band)
__device__ __forceinline__ void tile_mn(int t, int& mb, int& nb) {
    const int band = t >> 7;
    const int rem = t & 127;
    mb = (band * 8 + (rem & 7)) * BM;
    nb = (rem >> 3) * BN;
}

// ----------------------------------------------------------------------------
// Persistent GEMM (UNCHANGED from the 606.8us best): 128x256x128 CTA tile,
// 2-stage cp.async ring continuous across tiles, 8 warps (2M x 4N), warp
// tile 64x64 mma.sync m16n8k16, fused pi-quantize epilogue overlapped with
// the next tile's loads.
// ----------------------------------------------------------------------------
__global__ void __launch_bounds__(256, 1)
gemm_kernel(const float* __restrict__ bias, float* __restrict__ out) {
    extern __shared__ __align__(1024) char smem[];
    const uint32_t sbase = smem_u32(smem);
    const int tid = threadIdx.x;
    const int lane = tid & 31;
    const int w = tid >> 5;
    const int grid = gridDim.x;

    // per-thread loader constants
    const uint32_t toff = ((uint32_t)(tid >> 4) << 8) +
                          ((uint32_t)((tid & 15) ^ ((tid >> 4) & 15)) << 4);
    const int trow = tid >> 4;
    const int tk8  = (tid & 15) * 8;

    // ---- load cursor: one k-stage ahead, continuous across tiles ----
    int ld_tile = blockIdx.x;
    int ld_k = 0;
    int lmb, lnb;
    tile_mn(ld_tile, lmb, lnb);
    const __half* srcA = g_A16 + (size_t)(lmb + trow) * K_DIM + tk8;
    const __half* srcB = g_B16 + (size_t)(lnb + trow) * K_DIM + tk8;

    // prologue: fill stage 0 with first tile's kt0
    {
        const uint32_t dA = sbase + toff;
        const uint32_t dB = dA + A_STAGE_BYTES;
#pragma unroll
        for (int i = 0; i < 8; i++)  LOAD_A(i);
#pragma unroll
        for (int i = 0; i < 16; i++) LOAD_B(i);
        CP_COMMIT();
    }
    ld_k = BK; srcA += BK; srcB += BK;

    const int mwarp = w >> 2;        // 0..1 -> 64-row slices
    const int nwarp = w & 3;         // 0..3 -> 64-col slices

    const int x15a = lane & 15;                              // A row mod 16
    const int x15b = (lane & 7) | (((lane >> 4) & 1) << 3);  // B row mod 16
    uint32_t aoff[4], boff[4];
#pragma unroll
    for (int mi = 0; mi < 4; mi++)
        aoff[mi] = (uint32_t)((mwarp * 64 + mi * 16 + x15a) << 8);
#pragma unroll
    for (int nb = 0; nb < 4; nb++)
        boff[nb] = (uint32_t)(A_STAGE_BYTES + ((nwarp * 64 + nb * 16 + x15b) << 8));
    const int acol = lane >> 4;
    const int bcol = (lane >> 3) & 1;

    const int tr = lane >> 2;
    const int tc = (lane & 3) * 2;

    float acc[4][8][4];
#pragma unroll
    for (int mi = 0; mi < 4; mi++)
#pragma unroll
        for (int nj = 0; nj < 8; nj++)
#pragma unroll
            for (int e = 0; e < 4; e++) acc[mi][nj][e] = 0.f;

    int gk = 0;   // global k counter -> stage parity, continuous across tiles

    for (int tile = blockIdx.x; tile < TOTAL_TILES; tile += grid) {
        int mbase, nbase;
        tile_mn(tile, mbase, nbase);

        for (int kt = 0; kt < KT; kt++) {
            CP_WAIT0();
            __syncthreads();
            const int cur = gk & 1;
            const uint32_t st = sbase + cur * STAGE_BYTES;
            const uint32_t dA = sbase + (cur ^ 1) * STAGE_BYTES + toff;
            const uint32_t dB = dA + A_STAGE_BYTES;
            const bool more = (ld_tile < TOTAL_TILES);
#pragma unroll
            for (int ks = 0; ks < 8; ks++) {
                uint32_t a[4][4], b[4][4];
#pragma unroll
                for (int nb = 0; nb < 4; nb++)
                    LDSM4(b[nb], st + boff[nb] +
                          ((uint32_t)((ks * 2 + bcol) ^ x15b) << 4));
#pragma unroll
                for (int mi = 0; mi < 4; mi++)
                    LDSM4(a[mi], st + aoff[mi] +
                          ((uint32_t)((ks * 2 + acol) ^ x15a) << 4));
#pragma unroll
                for (int mi = 0; mi < 4; mi++)
#pragma unroll
                    for (int nj = 0; nj < 8; nj++)
                        MMA16816(acc[mi][nj], a[mi],
                                 b[nj >> 1][(nj & 1) * 2], b[nj >> 1][(nj & 1) * 2 + 1]);
                // next-stage loads: 8 chunks at ks=0,1,2; commit at ks=2
                if (more) {
                    switch (ks) {
                        case 0:
                            LOAD_A(0); LOAD_A(1); LOAD_A(2); LOAD_A(3);
                            LOAD_A(4); LOAD_A(5); LOAD_A(6); LOAD_A(7);
                            break;
                        case 1:
                            LOAD_B(0); LOAD_B(1); LOAD_B(2); LOAD_B(3);
                            LOAD_B(4); LOAD_B(5); LOAD_B(6); LOAD_B(7);
                            break;
                        case 2:
                            LOAD_B(8);  LOAD_B(9);  LOAD_B(10); LOAD_B(11);
                            LOAD_B(12); LOAD_B(13); LOAD_B(14); LOAD_B(15);
                            CP_COMMIT();
                            break;
                        default: break;
                    }
                }
            }
            gk++;
            if (more) {
                ld_k += BK;
                if (ld_k == K_DIM) {
                    ld_k = 0;
                    ld_tile += grid;
                    if (ld_tile < TOTAL_TILES) {
                        tile_mn(ld_tile, lmb, lnb);
                        srcA = g_A16 + (size_t)(lmb + trow) * K_DIM + tk8;
                        srcB = g_B16 + (size_t)(lnb + trow) * K_DIM + tk8;
                    }
                } else {
                    srcA += BK;
                    srcB += BK;
                }
            }
        }

        // ---- epilogue (overlaps the next tile's in-flight loads) ----
        const int row0 = mbase + mwarp * 64;
        const int col0 = nbase + nwarp * 64;
        float bv[16];
#pragma unroll
        for (int nj = 0; nj < 8; nj++) {
            bv[nj * 2]     = __ldg(bias + col0 + nj * 8 + tc);
            bv[nj * 2 + 1] = __ldg(bias + col0 + nj * 8 + tc + 1);
        }
#pragma unroll
        for (int mi = 0; mi < 4; mi++) {
#pragma unroll
            for (int rr = 0; rr < 2; rr++) {
                const int row = row0 + mi * 16 + rr * 8 + tr;
                float* orow = out + (size_t)row * N_DIM + col0;
#pragma unroll
                for (int nj = 0; nj < 8; nj++) {
                    const int c = nj * 8 + tc;
                    float2 o;
#pragma unroll
                    for (int e = 0; e < 2; e++) {
                        const float sv = acc[mi][nj][rr * 2 + e];    // exact int S
                        const float q  = rintf(__fmul_rn(sv, U_F)); // round(S*u)
                        const float cv = __fmul_rn(q, U_F);         // qz(dot)
                        const float tv = cv + bv[nj * 2 + e];       // + bias
                        (&o.x)[e] = __fmul_rn(rintf(__fmul_rn(tv, INVU_F)), U_F);
                    }
                    *reinterpret_cast<float2*>(orow + c) = o;
                }
            }
        }
#pragma unroll
        for (int mi = 0; mi < 4; mi++)
#pragma unroll
            for (int nj = 0; nj < 8; nj++)
#pragma unroll
                for (int e = 0; e < 4; e++) acc[mi][nj][e] = 0.f;
    }
}

// ----------------------------------------------------------------------------
// Host launcher (graph-capturable: kernel launches only)
// ----------------------------------------------------------------------------
extern "C" void kernel_launch(void* const* d_in, const int* in_sizes, int n_in,
                              void* d_out, int out_size) {
    const float* x = (const float*)d_in[0];   // [8192, 4096]
    const float* wgt = (const float*)d_in[1]; // [4096, 4096]
    const float* b = (const float*)d_in[2];   // [4096]
    float* out = (float*)d_out;               // [8192, 4096]

    void* a16 = nullptr; void* b16 = nullptr;
    cudaGetSymbolAddress(&a16, g_A16);
    cudaGetSymbolAddress(&b16, g_B16);

    quant2_kernel<<<QX_BLKS + QW_BLKS, 512>>>(x, (__half*)a16, wgt, (__half*)b16);

    static int sm_count = 0;
    if (sm_count == 0) {
        cudaDeviceGetAttribute(&sm_count, cudaDevAttrMultiProcessorCount, 0);
        if (sm_count <= 0) sm_count = 148;
        cudaFuncSetAttribute(gemm_kernel,
                             cudaFuncAttributeMaxDynamicSharedMemorySize, SMEM_SIZE);
    }
    gemm_kernel<<<sm_count, 256, SMEM_SIZE>>>(b, out);
}

// round 15
// speedup vs baseline: 1.2076x; 1.0439x over previous
#include <cuda_runtime.h>
#include <cuda_fp16.h>
#include <cstdint>

// ============================================================================
// PiLinear: out = qz(qz(x) @ qz(W)^T + b), qz(v) = round(v/u)*u, u = (pi/2)/256
//
// Exact-integer path: i = round(x/u), j = round(w/u) exact in f16; f16 MMA
// with f32 accumulation computes S = sum(i*j) exactly. Epilogue reconstructs
// round(S*u)*u (+bias, requantize).
//
// R15: mbarrier-decoupled pipeline with COOPERATIVE loading (fixes R12's
// single-producer LSU bottleneck). All 8 warps issue their cp.async chunks
// (R13 schedule) and post cp.async.mbarrier.arrive.noinc on full[s]
// (count=256); readers wait full[s], free stages via empty[s] (count=8).
// NO __syncthreads / wait_group in the mainloop -- warps skew up to one
// k-tile, covering each other's LDSM ramps (the ~900cy/kt rendezvous cost
// identified from tensor=81.6% == exact 4096cy HMMA floor / 5023cy per kt).
// ============================================================================

#define U_F   0.006135923151542565f   // (pi/2)/256
#define INVU_F 162.97466172610083f    // 512/pi

static constexpr int M_DIM = 8192;
static constexpr int N_DIM = 4096;
static constexpr int K_DIM = 4096;

static constexpr int BM = 128, BN = 256, BK = 128;
static constexpr int KT = K_DIM / BK;                         // 32 k-tiles
static constexpr int A_STAGE_BYTES = BM * BK * 2;             // 32768
static constexpr int B_STAGE_BYTES = BN * BK * 2;             // 65536
static constexpr int STAGE_BYTES = A_STAGE_BYTES + B_STAGE_BYTES;  // 98304
static constexpr uint32_t MBAR_OFF = 2 * STAGE_BYTES;         // 196608
static constexpr int SMEM_SIZE = 2 * STAGE_BYTES + 64;        // 196672

static constexpr int MTILES = M_DIM / BM;   // 64
static constexpr int NTILES = N_DIM / BN;   // 16
static constexpr int TOTAL_TILES = MTILES * NTILES;  // 1024

// Quantized f16-integer operand copies (scratch; no allocation allowed).
static __device__ __align__(128) __half g_A16[(size_t)M_DIM * K_DIM];
static __device__ __align__(128) __half g_B16[(size_t)N_DIM * K_DIM];

// ----------------------------------------------------------------------------
// PTX helpers
// ----------------------------------------------------------------------------
__device__ __forceinline__ uint32_t smem_u32(const void* p) {
    uint32_t a;
    asm("{ .reg .u64 t; cvta.to.shared.u64 t, %1; cvt.u32.u64 %0, t; }"
        : "=r"(a) : "l"(p));
    return a;
}

#define CP_ASYNC16(dst, src) \
    asm volatile("cp.async.cg.shared.global [%0], [%1], 16;" \
                 :: "r"(dst), "l"(src) : "memory")

#define MBAR_INIT(addr, cnt) \
    asm volatile("mbarrier.init.shared.b64 [%0], %1;" :: "r"(addr), "r"(cnt) : "memory")

#define MBAR_ARRIVE(addr) \
    asm volatile("mbarrier.arrive.shared.b64 _, [%0];" :: "r"(addr) : "memory")

// arrive on mbarrier when ALL prior cp.async of this thread complete;
// .noinc consumes one pre-registered expected arrival.
#define CPASYNC_MBAR_NOINC(addr) \
    asm volatile("cp.async.mbarrier.arrive.noinc.shared.b64 [%0];" \
                 :: "r"(addr) : "memory")

#define MBAR_WAIT(addr, parity) do {                                          \
    uint32_t _m = (addr); uint32_t _p = (parity); uint32_t _d;                \
    asm volatile("{ .reg .pred p;"                                           \
        " mbarrier.try_wait.parity.acquire.cta.shared::cta.b64 p, [%1], %2;" \
        " selp.b32 %0, 1, 0, p; }" : "=r"(_d) : "r"(_m), "r"(_p) : "memory");\
    if (!_d) {                                                                \
        asm volatile("{ .reg .pred P1;"                                      \
        " W%=: mbarrier.try_wait.parity.acquire.cta.shared::cta.b64 P1, [%0], %1, 0x989680;" \
        " @P1 bra.uni D%=; bra.uni W%=; D%=: }" :: "r"(_m), "r"(_p) : "memory"); \
    } } while (0)

#define LDSM4(r, addr) \
    asm volatile("ldmatrix.sync.aligned.m8n8.x4.shared.b16 {%0,%1,%2,%3}, [%4];" \
                 : "=r"((r)[0]), "=r"((r)[1]), "=r"((r)[2]), "=r"((r)[3]) \
                 : "r"(addr))

#define MMA16816(d, a, b0, b1) \
    asm volatile("mma.sync.aligned.m16n8k16.row.col.f32.f16.f16.f32 " \
                 "{%0,%1,%2,%3}, {%4,%5,%6,%7}, {%8,%9}, {%0,%1,%2,%3};" \
                 : "+f"((d)[0]), "+f"((d)[1]), "+f"((d)[2]), "+f"((d)[3]) \
                 : "r"((a)[0]), "r"((a)[1]), "r"((a)[2]), "r"((a)[3]), \
                   "r"(b0), "r"(b1))

// ----------------------------------------------------------------------------
// Quantize-to-f16 kernel (R14 version; DRAM turnaround-bound).
// ----------------------------------------------------------------------------
static constexpr int QX_BLKS = (int)(((size_t)M_DIM * K_DIM) / 8192);  // 4096
static constexpr int QW_BLKS = (int)(((size_t)N_DIM * K_DIM) / 8192);  // 2048

__device__ __forceinline__ uint2 quant_pack4(float4 v) {
    unsigned short h0 = __half_as_ushort(__float2half_rn(rintf(__fdiv_rn(v.x, U_F))));
    unsigned short h1 = __half_as_ushort(__float2half_rn(rintf(__fdiv_rn(v.y, U_F))));
    unsigned short h2 = __half_as_ushort(__float2half_rn(rintf(__fdiv_rn(v.z, U_F))));
    unsigned short h3 = __half_as_ushort(__float2half_rn(rintf(__fdiv_rn(v.w, U_F))));
    uint2 p;
    p.x = (uint32_t)h0 | ((uint32_t)h1 << 16);
    p.y = (uint32_t)h2 | ((uint32_t)h3 << 16);
    return p;
}

__global__ void __launch_bounds__(512) quant2_kernel(
    const float* __restrict__ x, __half* __restrict__ a,
    const float* __restrict__ wgt, __half* __restrict__ b) {
    const int bid = blockIdx.x;
    const float* s;
    __half* d;
    size_t base;
    if (bid < QX_BLKS) { s = x;   d = a; base = (size_t)bid * 8192; }
    else               { s = wgt; d = b; base = (size_t)(bid - QX_BLKS) * 8192; }
    const size_t i = base + (size_t)threadIdx.x * 16;

    const float4* sp = reinterpret_cast<const float4*>(s + i);
    float4 v0 = __ldcs(sp + 0);
    float4 v1 = __ldcs(sp + 1);
    float4 v2 = __ldcs(sp + 2);
    float4 v3 = __ldcs(sp + 3);

    uint2 p0 = quant_pack4(v0);
    uint2 p1 = quant_pack4(v1);
    uint2 p2 = quant_pack4(v2);
    uint2 p3 = quant_pack4(v3);

    uint4* dp = reinterpret_cast<uint4*>(d + i);
    dp[0] = make_uint4(p0.x, p0.y, p1.x, p1.y);
    dp[1] = make_uint4(p2.x, p2.y, p3.x, p3.y);
}

// Per-thread chunk strides (256B smem rows, 16 rows per chunk step).
static constexpr size_t SRC_STEP = (size_t)16 * K_DIM;   // halves
static constexpr uint32_t DST_STEP = 16 * 256;           // bytes

#define LOAD_A(i) CP_ASYNC16(dA + (i) * DST_STEP, srcA + (size_t)(i) * SRC_STEP)
#define LOAD_B(i) CP_ASYNC16(dB + (i) * DST_STEP, srcB + (size_t)(i) * SRC_STEP)

// banded rasterization: 8 m-tiles x 16 n-tiles per band (128 tiles/band)
__device__ __forceinline__ void tile_mn(int t, int& mb, int& nb) {
    const int band = t >> 7;
    const int rem = t & 127;
    mb = (band * 8 + (rem & 7)) * BM;
    nb = (rem >> 3) * BN;
}

// ----------------------------------------------------------------------------
// Persistent GEMM, mbarrier-decoupled, cooperative loads. 128x256x128 tile,
// 2-stage ring, 8 warps (2M x 4N), warp tile 64x64, fused quantize epilogue.
// full[s]: count 256, flipped by cp.async.mbarrier.arrive.noinc from every
// thread. empty[s]: count 8, one arrive per warp after last MMA of the stage.
// ----------------------------------------------------------------------------
__global__ void __launch_bounds__(256, 1)
gemm_kernel(const float* __restrict__ bias, float* __restrict__ out) {
    extern __shared__ __align__(1024) char smem[];
    const uint32_t sbase = smem_u32(smem);
    const uint32_t mb0 = sbase + MBAR_OFF;   // full[0],full[1],empty[0],empty[1]
    const int tid = threadIdx.x;
    const int lane = tid & 31;
    const int w = tid >> 5;
    const int grid = gridDim.x;

    if (tid == 0) {
        MBAR_INIT(mb0 + 0, 256);  // full[0]
        MBAR_INIT(mb0 + 8, 256);  // full[1]
        MBAR_INIT(mb0 + 16, 8);   // empty[0]
        MBAR_INIT(mb0 + 24, 8);   // empty[1]
    }
    __syncthreads();              // only block-wide barrier (init visibility)

    // per-thread loader constants
    const uint32_t toff = ((uint32_t)(tid >> 4) << 8) +
                          ((uint32_t)((tid & 15) ^ ((tid >> 4) & 15)) << 4);
    const int trow = tid >> 4;
    const int tk8  = (tid & 15) * 8;

    // ---- load cursor: one k-stage ahead, continuous across tiles ----
    int ld_tile = blockIdx.x;
    int ld_k = 0;
    int lmb, lnb;
    tile_mn(ld_tile, lmb, lnb);
    const __half* srcA = g_A16 + (size_t)(lmb + trow) * K_DIM + tk8;
    const __half* srcB = g_B16 + (size_t)(lnb + trow) * K_DIM + tk8;

    // prologue: fill stage 0 with first tile's kt0, signal full[0]
    {
        const uint32_t dA = sbase + toff;
        const uint32_t dB = dA + A_STAGE_BYTES;
#pragma unroll
        for (int i = 0; i < 8; i++)  LOAD_A(i);
#pragma unroll
        for (int i = 0; i < 16; i++) LOAD_B(i);
        CPASYNC_MBAR_NOINC(mb0 + 0);
    }
    ld_k = BK; srcA += BK; srcB += BK;

    const int mwarp = w >> 2;        // 0..1 -> 64-row slices
    const int nwarp = w & 3;         // 0..3 -> 64-col slices

    const int x15a = lane & 15;                              // A row mod 16
    const int x15b = (lane & 7) | (((lane >> 4) & 1) << 3);  // B row mod 16
    uint32_t aoff[4], boff[4];
#pragma unroll
    for (int mi = 0; mi < 4; mi++)
        aoff[mi] = (uint32_t)((mwarp * 64 + mi * 16 + x15a) << 8);
#pragma unroll
    for (int nb = 0; nb < 4; nb++)
        boff[nb] = (uint32_t)(A_STAGE_BYTES + ((nwarp * 64 + nb * 16 + x15b) << 8));
    const int acol = lane >> 4;
    const int bcol = (lane >> 3) & 1;

    const int tr = lane >> 2;
    const int tc = (lane & 3) * 2;

    float acc[4][8][4];
#pragma unroll
    for (int mi = 0; mi < 4; mi++)
#pragma unroll
        for (int nj = 0; nj < 8; nj++)
#pragma unroll
            for (int e = 0; e < 4; e++) acc[mi][nj][e] = 0.f;

    int gk = 0;   // global k counter -> stage parity, continuous across tiles

    for (int tile = blockIdx.x; tile < TOTAL_TILES; tile += grid) {
        int mbase, nbase;
        tile_mn(tile, mbase, nbase);

        for (int kt = 0; kt < KT; kt++) {
            const int cur = gk & 1;
            // reader gate: stage holds data for gk
            MBAR_WAIT(mb0 + cur * 8, (uint32_t)((gk >> 1) & 1));
            const uint32_t st = sbase + cur * STAGE_BYTES;
            const uint32_t dA = sbase + (cur ^ 1) * STAGE_BYTES + toff;
            const uint32_t dB = dA + A_STAGE_BYTES;
            const bool more = (ld_tile < TOTAL_TILES);
            // writer gate parity for stage cur^1 (data gk+1)
            const uint32_t eph = (uint32_t)((((gk + 1) >> 1) & 1) ^ 1);
#pragma unroll
            for (int ks = 0; ks < 8; ks++) {
                uint32_t a[4][4], b[4][4];
#pragma unroll
                for (int nb = 0; nb < 4; nb++)
                    LDSM4(b[nb], st + boff[nb] +
                          ((uint32_t)((ks * 2 + bcol) ^ x15b) << 4));
#pragma unroll
                for (int mi = 0; mi < 4; mi++)
                    LDSM4(a[mi], st + aoff[mi] +
                          ((uint32_t)((ks * 2 + acol) ^ x15a) << 4));
#pragma unroll
                for (int mi = 0; mi < 4; mi++)
#pragma unroll
                    for (int nj = 0; nj < 8; nj++)
                        MMA16816(acc[mi][nj], a[mi],
                                 b[nj >> 1][(nj & 1) * 2], b[nj >> 1][(nj & 1) * 2 + 1]);
                // next-stage loads: A at ks=0 (after writer gate), B at ks=1,2
                if (more) {
                    switch (ks) {
                        case 0:
                            MBAR_WAIT(mb0 + 16 + (cur ^ 1) * 8, eph);
                            LOAD_A(0); LOAD_A(1); LOAD_A(2); LOAD_A(3);
                            LOAD_A(4); LOAD_A(5); LOAD_A(6); LOAD_A(7);
                            break;
                        case 1:
                            LOAD_B(0); LOAD_B(1); LOAD_B(2); LOAD_B(3);
                            LOAD_B(4); LOAD_B(5); LOAD_B(6); LOAD_B(7);
                            break;
                        case 2:
                            LOAD_B(8);  LOAD_B(9);  LOAD_B(10); LOAD_B(11);
                            LOAD_B(12); LOAD_B(13); LOAD_B(14); LOAD_B(15);
                            CPASYNC_MBAR_NOINC(mb0 + (cur ^ 1) * 8);
                            break;
                        default: break;
                    }
                }
            }
            // free this stage: last MMA consumed the final LDSM fragments
            if (lane == 0) MBAR_ARRIVE(mb0 + 16 + cur * 8);
            gk++;
            if (more) {
                ld_k += BK;
                if (ld_k == K_DIM) {
                    ld_k = 0;
                    ld_tile += grid;
                    if (ld_tile < TOTAL_TILES) {
                        tile_mn(ld_tile, lmb, lnb);
                        srcA = g_A16 + (size_t)(lmb + trow) * K_DIM + tk8;
                        srcB = g_B16 + (size_t)(lnb + trow) * K_DIM + tk8;
                    }
                } else {
                    srcA += BK;
                    srcB += BK;
                }
            }
        }

        // ---- epilogue (per-warp; other warps may already run next tile) ----
        const int row0 = mbase + mwarp * 64;
        const int col0 = nbase + nwarp * 64;
        float bv[16];
#pragma unroll
        for (int nj = 0; nj < 8; nj++) {
            bv[nj * 2]     = __ldg(bias + col0 + nj * 8 + tc);
            bv[nj * 2 + 1] = __ldg(bias + col0 + nj * 8 + tc + 1);
        }
#pragma unroll
        for (int mi = 0; mi < 4; mi++) {
#pragma unroll
            for (int rr = 0; rr < 2; rr++) {
                const int row = row0 + mi * 16 + rr * 8 + tr;
                float* orow = out + (size_t)row * N_DIM + col0;
#pragma unroll
                for (int nj = 0; nj < 8; nj++) {
                    const int c = nj * 8 + tc;
                    float2 o;
#pragma unroll
                    for (int e = 0; e < 2; e++) {
                        const float sv = acc[mi][nj][rr * 2 + e];    // exact int S
                        const float q  = rintf(__fmul_rn(sv, U_F)); // round(S*u)
                        const float cv = __fmul_rn(q, U_F);         // qz(dot)
                        const float tv = cv + bv[nj * 2 + e];       // + bias
                        (&o.x)[e] = __fmul_rn(rintf(__fmul_rn(tv, INVU_F)), U_F);
                    }
                    *reinterpret_cast<float2*>(orow + c) = o;
                }
            }
        }
#pragma unroll
        for (int mi = 0; mi < 4; mi++)
#pragma unroll
            for (int nj = 0; nj < 8; nj++)
#pragma unroll
                for (int e = 0; e < 4; e++) acc[mi][nj][e] = 0.f;
    }
}

// ----------------------------------------------------------------------------
// Host launcher (graph-capturable: kernel launches only)
// ----------------------------------------------------------------------------
extern "C" void kernel_launch(void* const* d_in, const int* in_sizes, int n_in,
                              void* d_out, int out_size) {
    const float* x = (const float*)d_in[0];   // [8192, 4096]
    const float* wgt = (const float*)d_in[1]; // [4096, 4096]
    const float* b = (const float*)d_in[2];   // [4096]
    float* out = (float*)d_out;               // [8192, 4096]

    void* a16 = nullptr; void* b16 = nullptr;
    cudaGetSymbolAddress(&a16, g_A16);
    cudaGetSymbolAddress(&b16, g_B16);

    quant2_kernel<<<QX_BLKS + QW_BLKS, 512>>>(x, (__half*)a16, wgt, (__half*)b16);

    static int sm_count = 0;
    if (sm_count == 0) {
        cudaDeviceGetAttribute(&sm_count, cudaDevAttrMultiProcessorCount, 0);
        if (sm_count <= 0) sm_count = 148;
        cudaFuncSetAttribute(gemm_kernel,
                             cudaFuncAttributeMaxDynamicSharedMemorySize, SMEM_SIZE);
    }
    gemm_kernel<<<sm_count, 256, SMEM_SIZE>>>(b, out);
}